// round 3
// baseline (speedup 1.0000x reference)
#include <cuda_runtime.h>

// Fixed problem shapes
#define BB 16
#define TT 288
#define NN 4096
#define HH 10
#define RR 16
#define TCHUNKS 9
#define TPC (TT / TCHUNKS)            // 32
#define XBLK 8                        // blocks along n (256 thr * 2 nodes = 512 n / block)
#define NBLKS1 (XBLK * BB * TCHUNKS)  // 1152
#define K3X 16                        // n-chunks in k2 (256 nodes each)
#define NBLKS2 (K3X * BB)             // 256

// Scratch: everything read is written earlier in the SAME replay (or is a
// counter that the last block resets to 0) -> graph-replay safe.
__device__ float g_sum[TCHUNKS][BB][NN];
__device__ float g_cnt[TCHUNKS][BB][NN];
__device__ float g_blk_s[NBLKS1];
__device__ float g_blk_c[NBLKS1];
__device__ float g_gmean;
__device__ float g_rcnt[RR];
__device__ float g_regp[BB][K3X][RR];
__device__ unsigned int g_ctr1;   // zero at load; last block restores 0
__device__ unsigned int g_ctr2;

// ---------------------------------------------------------------------------
// Kernel 1: single heavy pass over 151MB (float4 streaming). 1152 blocks x 256.
// Each thread: 2 adjacent nodes over TPC=32 timesteps. Block-reduces (sum,cnt).
// The LAST block then computes gmean + per-region node counts (absorbs old k2).
// ---------------------------------------------------------------------------
__global__ void __launch_bounds__(256) k1_main(const float4* __restrict__ data,
                                               const int* __restrict__ cid) {
    const int tid = threadIdx.x;
    const int b   = blockIdx.y;
    const int tc  = blockIdx.z;
    const int q   = blockIdx.x * 256 + tid;   // float4 column in [0, NN/2)
    const int n0  = q * 2;

    const float4* __restrict__ p =
        data + (size_t)(b * TT + tc * TPC) * (NN / 2) + q;

    float s0 = 0.f, s1 = 0.f, c0 = 0.f, c1 = 0.f;
    #pragma unroll 8
    for (int t = 0; t < TPC; ++t) {
        float4 v = __ldcs(p);
        p += NN / 2;
        if (v.x != -1.0f) { s0 += v.x; c0 += 1.0f; }
        if (v.z != -1.0f) { s1 += v.z; c1 += 1.0f; }
    }
    g_sum[tc][b][n0]     = s0;
    g_sum[tc][b][n0 + 1] = s1;
    g_cnt[tc][b][n0]     = c0;
    g_cnt[tc][b][n0 + 1] = c1;

    // Block-reduce total (sum, cnt)
    float s = s0 + s1;
    float c = c0 + c1;
    #pragma unroll
    for (int o = 16; o > 0; o >>= 1) {
        s += __shfl_down_sync(0xffffffffu, s, o);
        c += __shfl_down_sync(0xffffffffu, c, o);
    }
    __shared__ float sh_s[8], sh_c[8];
    const int wid = tid >> 5, lane = tid & 31;
    if (lane == 0) { sh_s[wid] = s; sh_c[wid] = c; }
    __syncthreads();
    if (wid == 0) {
        s = (lane < 8) ? sh_s[lane] : 0.f;
        c = (lane < 8) ? sh_c[lane] : 0.f;
        #pragma unroll
        for (int o = 4; o > 0; o >>= 1) {
            s += __shfl_down_sync(0xffffffffu, s, o);
            c += __shfl_down_sync(0xffffffffu, c, o);
        }
        if (lane == 0) {
            const int bid = (blockIdx.z * BB + blockIdx.y) * XBLK + blockIdx.x;
            g_blk_s[bid] = s;
            g_blk_c[bid] = c;
        }
    }

    // ---- last-block-done: gmean + region counts ----
    __shared__ bool amLast;
    if (tid == 0) {
        __threadfence();
        amLast = (atomicAdd(&g_ctr1, 1u) == NBLKS1 - 1);
    }
    __syncthreads();
    if (!amLast) return;

    __shared__ float rc[RR];
    if (tid < RR) rc[tid] = 0.f;
    __syncthreads();
    for (int i = tid; i < NN; i += 256)
        atomicAdd(&rc[cid[i]], 1.0f);

    float ts = 0.f, tcn = 0.f;
    for (int i = tid; i < NBLKS1; i += 256) {
        ts  += g_blk_s[i];
        tcn += g_blk_c[i];
    }
    #pragma unroll
    for (int o = 16; o > 0; o >>= 1) {
        ts  += __shfl_down_sync(0xffffffffu, ts, o);
        tcn += __shfl_down_sync(0xffffffffu, tcn, o);
    }
    if (lane == 0) { sh_s[wid] = ts; sh_c[wid] = tcn; }
    __syncthreads();
    if (tid == 0) {
        ts = 0.f; tcn = 0.f;
        #pragma unroll
        for (int w = 0; w < 8; ++w) { ts += sh_s[w]; tcn += sh_c[w]; }
        g_gmean = ts / fmaxf(tcn, 1.0f);
        g_ctr1  = 0;               // reset for next graph replay
    }
    if (tid < RR) g_rcnt[tid] = rc[tid];
}

// ---------------------------------------------------------------------------
// Kernel 2: per-(b,n) imputed time-mean -> pred_speed (tiled H=10) + regional
// partials; LAST block reduces partials and writes regional output (old k4).
// grid = (K3X, BB) = 256 blocks x 256 thr, one node per thread.
// ---------------------------------------------------------------------------
__global__ void __launch_bounds__(256) k2_outputs(const int* __restrict__ cid,
                                                  float* __restrict__ out) {
    const int b   = blockIdx.y;
    const int n   = blockIdx.x * 256 + threadIdx.x;
    const int tid = threadIdx.x;

    __shared__ float rs[RR];
    if (tid < RR) rs[tid] = 0.f;
    __syncthreads();

    const float gm   = g_gmean;
    const float invT = 1.0f / (float)TT;

    float s = 0.f, c = 0.f;
    #pragma unroll
    for (int tc = 0; tc < TCHUNKS; ++tc) {
        s += g_sum[tc][b][n];
        c += g_cnt[tc][b][n];
    }
    const float mean = (s + ((float)TT - c) * gm) * invT;

    #pragma unroll
    for (int h = 0; h < HH; ++h)
        out[((size_t)b * HH + h) * NN + n] = mean;

    atomicAdd(&rs[cid[n]], mean);
    __syncthreads();
    if (tid < RR)
        g_regp[b][blockIdx.x][tid] = rs[tid];

    // ---- last-block-done: regional output ----
    __shared__ bool amLast;
    if (tid == 0) {
        __threadfence();
        amLast = (atomicAdd(&g_ctr2, 1u) == NBLKS2 - 1);
    }
    __syncthreads();
    if (!amLast) return;

    // tid -> (bb, r); sum 16 n-chunk partials, divide, tile over H
    const int bb = tid >> 4;
    const int r  = tid & 15;
    float acc = 0.f;
    #pragma unroll
    for (int x = 0; x < K3X; ++x)
        acc += g_regp[bb][x][r];
    const float v = acc / fmaxf(g_rcnt[r], 1.0f);

    float* __restrict__ ro = out + (size_t)BB * HH * NN;
    #pragma unroll
    for (int h = 0; h < HH; ++h)
        ro[((size_t)bb * HH + h) * RR + r] = v;

    if (tid == 0) g_ctr2 = 0;      // reset for next graph replay
}

// ---------------------------------------------------------------------------
extern "C" void kernel_launch(void* const* d_in, const int* in_sizes, int n_in,
                              void* d_out, int out_size) {
    const float4* data = (const float4*)d_in[0];
    const int*    cid  = (const int*)d_in[1];
    float*        out  = (float*)d_out;

    dim3 g1(XBLK, BB, TCHUNKS);   // (8, 16, 9) = 1152 blocks
    k1_main<<<g1, 256>>>(data, cid);
    dim3 g2(K3X, BB);             // 256 blocks
    k2_outputs<<<g2, 256>>>(cid, out);
}

// round 4
// speedup vs baseline: 1.0988x; 1.0988x over previous
#include <cuda_runtime.h>

// Fixed problem shapes
#define BB 16
#define TT 288
#define NN 4096
#define HH 10
#define RR 16
#define TCHUNKS 9
#define TPC (TT / TCHUNKS)            // 32
#define XBLK 8                        // k1 blocks along n (256 thr * 2 nodes)
#define NBLKS1 (XBLK * BB * TCHUNKS)  // 1152
#define K2X (NN / 256)                // 16 n-chunks in k2
#define NBLKS2 (K2X * BB)             // 256

// Scratch: written every replay before being read; counter restored to 0 by
// the last block each replay -> graph-replay safe.
__device__ float4 g_part[TCHUNKS][BB][NN / 2];  // (s0,c0,s1,c1) per node pair
__device__ float2 g_blk[NBLKS1];                // per-k1-block (sum, cnt)
__device__ float  g_regp[BB][K2X][RR];          // regional partial sums
__device__ unsigned int g_ctr;                  // zero at load; restored each replay

// ---------------------------------------------------------------------------
// Kernel 1: the single heavy pass over 151MB (float4 streaming loads).
// grid (8,16,9) = 1152 blocks x 256 thr; each thread: 2 adjacent nodes x 32 t.
// ---------------------------------------------------------------------------
__global__ void __launch_bounds__(256) k1_main(const float4* __restrict__ data) {
    const int tid = threadIdx.x;
    const int b   = blockIdx.y;
    const int tc  = blockIdx.z;
    const int q   = blockIdx.x * 256 + tid;   // float4 column in [0, NN/2)

    const float4* __restrict__ p =
        data + (size_t)(b * TT + tc * TPC) * (NN / 2) + q;

    float s0 = 0.f, s1 = 0.f, c0 = 0.f, c1 = 0.f;
    #pragma unroll 8
    for (int t = 0; t < TPC; ++t) {
        float4 v = __ldcs(p);
        p += NN / 2;
        if (v.x != -1.0f) { s0 += v.x; c0 += 1.0f; }
        if (v.z != -1.0f) { s1 += v.z; c1 += 1.0f; }
    }
    g_part[tc][b][q] = make_float4(s0, c0, s1, c1);

    // Block-reduce total (sum, cnt) -> g_blk
    float s = s0 + s1;
    float c = c0 + c1;
    #pragma unroll
    for (int o = 16; o > 0; o >>= 1) {
        s += __shfl_down_sync(0xffffffffu, s, o);
        c += __shfl_down_sync(0xffffffffu, c, o);
    }
    __shared__ float sh_s[8], sh_c[8];
    const int wid = tid >> 5, lane = tid & 31;
    if (lane == 0) { sh_s[wid] = s; sh_c[wid] = c; }
    __syncthreads();
    if (tid == 0) {
        s = 0.f; c = 0.f;
        #pragma unroll
        for (int w = 0; w < 8; ++w) { s += sh_s[w]; c += sh_c[w]; }
        const int bid = (blockIdx.z * BB + blockIdx.y) * XBLK + blockIdx.x;
        g_blk[bid] = make_float2(s, c);
    }
}

// ---------------------------------------------------------------------------
// Kernel 2: grid (K2X, BB) = 256 blocks x 1024 thr (86% occ).
// Every block: (a) redundantly reduces g_blk (9KB, L2-hot) -> gmean,
// (b) 4 thread-groups x 256 nodes load tc-partials in parallel,
// (c) threads<256 finish mean + regional shared atomics,
// (d) all 1024 threads write the H=10 tiled pred_speed (2-3 stores each).
// Last block writes the regional output (tiny tail) and resets the counter.
// ---------------------------------------------------------------------------
__global__ void __launch_bounds__(1024) k2_outputs(const int* __restrict__ cid,
                                                   float* __restrict__ out) {
    const int tid = threadIdx.x;
    const int b   = blockIdx.y;
    const int nb  = blockIdx.x * 256;
    const int n   = tid & 255;      // node within chunk
    const int grp = tid >> 8;       // 0..3
    const int ng  = nb + n;         // global node

    __shared__ float sh_s[4][256];
    __shared__ float sh_c[4][256];
    __shared__ float sh_mean[256];
    __shared__ float sh_red[32];
    __shared__ float sh_gm;
    __shared__ float rs[RR];

    if (tid < RR) rs[tid] = 0.f;

    // ---- (a) gmean from k1 block partials (redundant per block) ----
    float s = 0.f, c = 0.f;
    #pragma unroll
    for (int i = tid; i < NBLKS1; i += 1024) {
        float2 v = g_blk[i];
        s += v.x; c += v.y;
    }
    #pragma unroll
    for (int o = 16; o > 0; o >>= 1) {
        s += __shfl_down_sync(0xffffffffu, s, o);
        c += __shfl_down_sync(0xffffffffu, c, o);
    }
    const int wid = tid >> 5, lane = tid & 31;
    if (lane == 0) { sh_red[wid] = s; }
    __syncthreads();
    __shared__ float sh_red2[32];
    if (lane == 0) { sh_red2[wid] = c; }

    // ---- (b) tc-partial loads, 4 groups in parallel ----
    // float2 view of g_part: element ((tc*BB + b)*NN + node) = (sum, cnt)
    const float2* __restrict__ pv = (const float2*)&g_part[0][0][0];
    float ls = 0.f, lc = 0.f;
    #pragma unroll
    for (int tc = grp; tc < TCHUNKS; tc += 4) {
        float2 v = pv[(size_t)(tc * BB + b) * NN + ng];
        ls += v.x; lc += v.y;
    }
    sh_s[grp][n] = ls;
    sh_c[grp][n] = lc;
    __syncthreads();

    if (tid == 0) {
        float ts = 0.f, tc2 = 0.f;
        #pragma unroll
        for (int w = 0; w < 32; ++w) { ts += sh_red[w]; tc2 += sh_red2[w]; }
        sh_gm = ts / fmaxf(tc2, 1.0f);
    }
    __syncthreads();

    // ---- (c) finish mean + regional partials ----
    if (tid < 256) {
        float ss = sh_s[0][n] + sh_s[1][n] + sh_s[2][n] + sh_s[3][n];
        float cc = sh_c[0][n] + sh_c[1][n] + sh_c[2][n] + sh_c[3][n];
        float mean = (ss + ((float)TT - cc) * sh_gm) * (1.0f / (float)TT);
        sh_mean[n] = mean;
        atomicAdd(&rs[cid[ng]], mean);
    }
    __syncthreads();

    // ---- (d) tiled pred_speed stores ----
    const float mean = sh_mean[n];
    #pragma unroll
    for (int h = grp; h < HH; h += 4)
        out[((size_t)b * HH + h) * NN + ng] = mean;

    if (tid < RR)
        g_regp[b][blockIdx.x][tid] = rs[tid];

    // ---- last-block-done: regional output ----
    __shared__ bool amLast;
    __syncthreads();
    if (tid == 0) {
        __threadfence();
        amLast = (atomicAdd(&g_ctr, 1u) == NBLKS2 - 1);
    }
    __syncthreads();
    if (!amLast) return;

    __shared__ float rcnt[RR];
    if (tid < RR) rcnt[tid] = 0.f;
    __syncthreads();
    for (int i = tid; i < NN; i += 1024)
        atomicAdd(&rcnt[cid[i]], 1.0f);
    __syncthreads();

    if (tid < 256) {
        const int bb = tid >> 4;
        const int r  = tid & 15;
        float acc = 0.f;
        #pragma unroll
        for (int x = 0; x < K2X; ++x)
            acc += g_regp[bb][x][r];
        const float v = acc / fmaxf(rcnt[r], 1.0f);
        float* __restrict__ ro = out + (size_t)BB * HH * NN;
        #pragma unroll
        for (int h = 0; h < HH; ++h)
            ro[((size_t)bb * HH + h) * RR + r] = v;
    }
    if (tid == 0) g_ctr = 0;   // restore for next graph replay
}

// ---------------------------------------------------------------------------
extern "C" void kernel_launch(void* const* d_in, const int* in_sizes, int n_in,
                              void* d_out, int out_size) {
    const float4* data = (const float4*)d_in[0];
    const int*    cid  = (const int*)d_in[1];
    float*        out  = (float*)d_out;

    dim3 g1(XBLK, BB, TCHUNKS);   // 1152 blocks
    k1_main<<<g1, 256>>>(data);
    dim3 g2(K2X, BB);             // 256 blocks x 1024 thr
    k2_outputs<<<g2, 1024>>>(cid, out);
}